// round 1
// baseline (speedup 1.0000x reference)
#include <cuda_runtime.h>
#include <math.h>

#define Nn 8192
#define Dd 64
#define IN_F 128
#define TI 64
#define TJ 64

// ---------------- scratch (static device globals; no allocation) -------------
__device__ float g_xw_s[Nn * Dd];
__device__ float g_xw_t[Nn * Dd];
__device__ float g_s1[Nn], g_s2[Nn], g_t1[Nn], g_t2[Nn];
__device__ float g_max2[2];   // [0] = max(t2), [1] = max(s2)

// ---------------- packed fp32x2 helpers (sm_100a) ----------------------------
__device__ __forceinline__ unsigned long long pack2(float a, float b) {
    unsigned long long r;
    asm("mov.b64 %0, {%1,%2};" : "=l"(r) : "f"(a), "f"(b));
    return r;
}
__device__ __forceinline__ void unpack2(unsigned long long v, float& a, float& b) {
    asm("mov.b64 {%0,%1}, %2;" : "=f"(a), "=f"(b) : "l"(v));
}
__device__ __forceinline__ void ffma2(unsigned long long& d,
                                      unsigned long long a, unsigned long long b) {
    asm("fma.rn.f32x2 %0, %1, %2, %0;" : "+l"(d) : "l"(a), "l"(b));
}

__device__ __forceinline__ float leaky(float z) {
    // slope 0.01; max(z, 0.01z) == leaky_relu(z)
    return fmaxf(z, 0.01f * z);
}

// ---------------- P1: xw = x @ W for both matrices ---------------------------
__global__ void proj_kernel(const float* __restrict__ xs, const float* __restrict__ xt,
                            const float* __restrict__ ws, const float* __restrict__ wt) {
    int y = blockIdx.y;
    const float* x = y ? xt : xs;
    const float* W = y ? wt : ws;
    float* out = y ? g_xw_t : g_xw_s;

    __shared__ float Wsm[IN_F * Dd];   // 32 KB
    __shared__ float xsm[16 * IN_F];   // 8 KB

    int tid = threadIdx.x;
    const float4* W4 = (const float4*)W;
    float4* Ws4 = (float4*)Wsm;
    #pragma unroll
    for (int k = tid; k < IN_F * Dd / 4; k += 256) Ws4[k] = W4[k];

    int r0 = blockIdx.x * 16;
    const float4* x4 = (const float4*)(x + r0 * IN_F);
    float4* xs4 = (float4*)xsm;
    #pragma unroll
    for (int k = tid; k < 16 * IN_F / 4; k += 256) xs4[k] = x4[k];
    __syncthreads();

    int c = tid & 63, rq = tid >> 6;   // 64 cols x 4 row-groups
    float acc[4] = {0.f, 0.f, 0.f, 0.f};
    #pragma unroll 4
    for (int kk = 0; kk < IN_F; kk++) {
        float wv = Wsm[kk * Dd + c];
        #pragma unroll
        for (int k = 0; k < 4; k++)
            acc[k] += xsm[(rq + 4 * k) * IN_F + kk] * wv;
    }
    #pragma unroll
    for (int k = 0; k < 4; k++)
        out[(r0 + rq + 4 * k) * Dd + c] = acc[k];
}

// ---------------- P2: s1/s2 (from xw_s) and t1/t2 (from xw_t) ----------------
__global__ void proj_vec_kernel(const float* __restrict__ a) {
    int y = blockIdx.y;
    const float* xw = y ? g_xw_t : g_xw_s;
    int w = threadIdx.x >> 5, lane = threadIdx.x & 31;
    int row = blockIdx.x * 8 + w;

    float v0 = xw[row * Dd + lane];
    float v1 = xw[row * Dd + 32 + lane];
    float p1 = v0 * a[lane]      + v1 * a[32 + lane];   // dot with a1
    float p2 = v0 * a[64 + lane] + v1 * a[96 + lane];   // dot with a2
    #pragma unroll
    for (int o = 16; o; o >>= 1) {
        p1 += __shfl_down_sync(0xffffffffu, p1, o);
        p2 += __shfl_down_sync(0xffffffffu, p2, o);
    }
    if (lane == 0) {
        if (y == 0) { g_s1[row] = p1; g_s2[row] = p2; }
        else        { g_t1[row] = p1; g_t2[row] = p2; }
    }
}

// ---------------- P3: global maxes of t2 and s2 ------------------------------
__global__ void max_kernel() {
    __shared__ float sm[512];
    int tid = threadIdx.x;   // 256
    float m1 = -1e30f, m2 = -1e30f;
    for (int i = tid; i < Nn; i += 256) {
        m1 = fmaxf(m1, g_t2[i]);
        m2 = fmaxf(m2, g_s2[i]);
    }
    sm[tid] = m1; sm[256 + tid] = m2;
    __syncthreads();
    for (int s = 128; s; s >>= 1) {
        if (tid < s) {
            sm[tid]       = fmaxf(sm[tid],       sm[tid + s]);
            sm[256 + tid] = fmaxf(sm[256 + tid], sm[256 + tid + s]);
        }
        __syncthreads();
    }
    if (tid == 0) { g_max2[0] = sm[0]; g_max2[1] = sm[256]; }
}

// ---------------- main fused attention pass ----------------------------------
// p=0 (source): out_s[i,:] = elu( (1/den_i) * sum_j adj[i,j]*exp(leaky(s1_i+t2_j)-m_i)*xw_s[j,:] + bias_s )
// p=1 (target): out_t[i,:] = elu( (1/den_i) * sum_j adj[j,i]*exp(leaky(t1_i+s2_j)-m_i)*xw_t[j,:] + bias_t )
__global__ void __launch_bounds__(128)
attn_kernel(const int* __restrict__ adj,
            const float* __restrict__ bias_s, const float* __restrict__ bias_t,
            float* __restrict__ out) {
    int p = blockIdx.y;
    const float* xw   = p ? g_xw_t : g_xw_s;
    const float* sv   = p ? g_t1   : g_s1;
    const float* tv   = p ? g_s2   : g_t2;
    const float* bias = p ? bias_t : bias_s;
    float M = g_max2[p];
    int i0 = blockIdx.x * TI;

    __shared__ float s_wts[TI * (TJ + 1)];   // 16.25 KB (padded rows)
    __shared__ float s_x[TJ * Dd];           // 16 KB
    __shared__ float s_s[TI];
    __shared__ float s_m[TI];
    __shared__ float s_den[TI * 2];

    int tid = threadIdx.x;
    if (tid < TI) {
        float s = sv[i0 + tid];
        s_s[tid] = s;
        s_m[tid] = leaky(s + M);   // upper bound on row max (leaky monotone)
    }
    __syncthreads();

    int ig = tid >> 3;     // 0..15 : rows ig, ig+16, ig+32, ig+48
    int dg = tid & 7;      // 0..7  : d pairs dg+8c, c<4
    int fix = tid & 63;    // fixed index in weight phase
    int half = tid >> 6;   // 0/1

    // fixed-per-thread values for pass B (i-local = fix)
    float sB = s_s[fix];
    float mB = s_m[fix];

    unsigned long long acc[4][4];
    #pragma unroll
    for (int r = 0; r < 4; r++)
        #pragma unroll
        for (int c = 0; c < 4; c++) acc[r][c] = 0ull;
    float denp = 0.f;

    for (int jt = 0; jt < Nn / TJ; jt++) {
        int j0 = jt * TJ;
        __syncthreads();   // prev-tile readers done

        // load xw tile [TJ x Dd] (contiguous) into smem
        {
            const float4* xt4 = (const float4*)(xw + j0 * Dd);
            float4* sx4 = (float4*)s_x;
            #pragma unroll
            for (int k = 0; k < 8; k++)
                sx4[tid + 128 * k] = xt4[tid + 128 * k];
        }

        // weight phase: fill s_wts[i_local][j_local]
        if (p == 0) {
            float tvA = __ldg(&tv[j0 + fix]);   // column-side value, fixed per thread
            #pragma unroll 4
            for (int k = 0; k < 32; k++) {
                int ii = half + 2 * k;
                int av = adj[(i0 + ii) * Nn + (j0 + fix)];
                float sc = leaky(s_s[ii] + tvA);
                float msk = (av > 0) ? 1.f : 0.f;
                s_wts[ii * (TJ + 1) + fix] = msk * __expf(sc - s_m[ii]);
            }
        } else {
            #pragma unroll 4
            for (int k = 0; k < 32; k++) {
                int jr = half + 2 * k;
                int av = adj[(j0 + jr) * Nn + (i0 + fix)];
                float sc = leaky(sB + __ldg(&tv[j0 + jr]));
                float msk = (av > 0) ? 1.f : 0.f;
                s_wts[fix * (TJ + 1) + jr] = msk * __expf(sc - mB);
            }
        }
        __syncthreads();

        // accumulate: acc[r][c] += w(i_r, jj) * xw(jj, d_c) with packed fp32x2
        const unsigned long long* sx2 = (const unsigned long long*)s_x;
        #pragma unroll 4
        for (int jj = 0; jj < TJ; jj++) {
            unsigned long long w2[4];
            #pragma unroll
            for (int r = 0; r < 4; r++) {
                float w = s_wts[(ig + 16 * r) * (TJ + 1) + jj];
                w2[r] = pack2(w, w);
            }
            #pragma unroll
            for (int c = 0; c < 4; c++) {
                unsigned long long xv = sx2[jj * 32 + dg + 8 * c];
                #pragma unroll
                for (int r = 0; r < 4; r++) ffma2(acc[r][c], w2[r], xv);
            }
        }

        // denominator sweep over this tile's weights
        {
            int ii = tid >> 1, h = tid & 1;
            const float* wr = &s_wts[ii * (TJ + 1) + h * 32];
            float ps = 0.f;
            #pragma unroll
            for (int u = 0; u < 32; u++) ps += wr[u];
            denp += ps;
        }
    }

    // write den partials and finish
    {
        int ii = tid >> 1, h = tid & 1;
        s_den[ii * 2 + h] = denp;
    }
    __syncthreads();

    float* outp = out + (size_t)p * Nn * Dd;
    #pragma unroll
    for (int r = 0; r < 4; r++) {
        int il = ig + 16 * r;
        float den = s_den[il * 2] + s_den[il * 2 + 1];
        float inv = 1.f / den;
        int i = i0 + il;
        #pragma unroll
        for (int c = 0; c < 4; c++) {
            float lo, hi;
            unpack2(acc[r][c], lo, hi);
            int d = 2 * (dg + 8 * c);
            float v0 = lo * inv + bias[d];
            float v1 = hi * inv + bias[d + 1];
            v0 = (v0 > 0.f) ? v0 : expm1f(v0);
            v1 = (v1 > 0.f) ? v1 : expm1f(v1);
            ((float2*)(outp + (size_t)i * Dd))[dg + 8 * c] = make_float2(v0, v1);
        }
    }
}

// ---------------- launch ------------------------------------------------------
extern "C" void kernel_launch(void* const* d_in, const int* in_sizes, int n_in,
                              void* d_out, int out_size) {
    const float* xs  = (const float*)d_in[0];   // x_source [8192,128]
    const float* xt  = (const float*)d_in[1];   // x_target [8192,128]
    const int*   adj = (const int*)  d_in[2];   // adjacency [8192,8192]
    const float* ws  = (const float*)d_in[3];   // w_source [128,64]
    const float* wt  = (const float*)d_in[4];   // w_target [128,64]
    const float* a   = (const float*)d_in[5];   // a [128,1]
    const float* bs  = (const float*)d_in[6];   // bias_source [64]
    const float* bt  = (const float*)d_in[7];   // bias_target [64]
    float* out = (float*)d_out;                 // [2, 8192, 64]

    proj_kernel<<<dim3(Nn / 16, 2), 256>>>(xs, xt, ws, wt);
    proj_vec_kernel<<<dim3(Nn / 8, 2), 256>>>(a);
    max_kernel<<<1, 256>>>();
    attn_kernel<<<dim3(Nn / TI, 2), 128>>>(adj, bs, bt, out);
}

// round 2
// speedup vs baseline: 1.8918x; 1.8918x over previous
#include <cuda_runtime.h>
#include <math.h>

#define Nn 8192
#define Dd 64
#define IN_F 128
#define TI 64
#define TJ 64
#define SPLITS 8
#define JCH (Nn / SPLITS)   // 1024 j's per split

// ---------------- scratch (static device globals; no allocation) -------------
__device__ float g_xw_s[Nn * Dd];
__device__ float g_xw_t[Nn * Dd];
__device__ float g_s1[Nn], g_s2[Nn], g_t1[Nn], g_t2[Nn];
__device__ float g_max2[2];   // [0] = max(t2), [1] = max(s2)
__device__ float g_pnum[2 * SPLITS * Nn * Dd];   // 33.5 MB partial numerators
__device__ float g_pden[2 * SPLITS * Nn];        // 0.5 MB partial denominators

// ---------------- packed fp32x2 helpers (sm_100a) ----------------------------
__device__ __forceinline__ unsigned long long pack2(float a, float b) {
    unsigned long long r;
    asm("mov.b64 %0, {%1,%2};" : "=l"(r) : "f"(a), "f"(b));
    return r;
}
__device__ __forceinline__ void unpack2(unsigned long long v, float& a, float& b) {
    asm("mov.b64 {%0,%1}, %2;" : "=f"(a), "=f"(b) : "l"(v));
}
__device__ __forceinline__ void ffma2(unsigned long long& d,
                                      unsigned long long a, unsigned long long b) {
    asm("fma.rn.f32x2 %0, %1, %2, %0;" : "+l"(d) : "l"(a), "l"(b));
}

__device__ __forceinline__ float leaky(float z) {
    return fmaxf(z, 0.01f * z);   // slope 0.01
}

// ---------------- P1: xw = x @ W for both matrices ---------------------------
__global__ void proj_kernel(const float* __restrict__ xs, const float* __restrict__ xt,
                            const float* __restrict__ ws, const float* __restrict__ wt) {
    int y = blockIdx.y;
    const float* x = y ? xt : xs;
    const float* W = y ? wt : ws;
    float* out = y ? g_xw_t : g_xw_s;

    __shared__ float Wsm[IN_F * Dd];   // 32 KB
    __shared__ float xsm[16 * IN_F];   // 8 KB

    int tid = threadIdx.x;
    const float4* W4 = (const float4*)W;
    float4* Ws4 = (float4*)Wsm;
    #pragma unroll
    for (int k = tid; k < IN_F * Dd / 4; k += 256) Ws4[k] = W4[k];

    int r0 = blockIdx.x * 16;
    const float4* x4 = (const float4*)(x + r0 * IN_F);
    float4* xs4 = (float4*)xsm;
    #pragma unroll
    for (int k = tid; k < 16 * IN_F / 4; k += 256) xs4[k] = x4[k];
    __syncthreads();

    int c = tid & 63, rq = tid >> 6;
    float acc[4] = {0.f, 0.f, 0.f, 0.f};
    #pragma unroll 4
    for (int kk = 0; kk < IN_F; kk++) {
        float wv = Wsm[kk * Dd + c];
        #pragma unroll
        for (int k = 0; k < 4; k++)
            acc[k] += xsm[(rq + 4 * k) * IN_F + kk] * wv;
    }
    #pragma unroll
    for (int k = 0; k < 4; k++)
        out[(r0 + rq + 4 * k) * Dd + c] = acc[k];
}

// ---------------- P2: s1/s2 (from xw_s) and t1/t2 (from xw_t) ----------------
__global__ void proj_vec_kernel(const float* __restrict__ a) {
    int y = blockIdx.y;
    const float* xw = y ? g_xw_t : g_xw_s;
    int w = threadIdx.x >> 5, lane = threadIdx.x & 31;
    int row = blockIdx.x * 8 + w;

    float v0 = xw[row * Dd + lane];
    float v1 = xw[row * Dd + 32 + lane];
    float p1 = v0 * a[lane]      + v1 * a[32 + lane];
    float p2 = v0 * a[64 + lane] + v1 * a[96 + lane];
    #pragma unroll
    for (int o = 16; o; o >>= 1) {
        p1 += __shfl_down_sync(0xffffffffu, p1, o);
        p2 += __shfl_down_sync(0xffffffffu, p2, o);
    }
    if (lane == 0) {
        if (y == 0) { g_s1[row] = p1; g_s2[row] = p2; }
        else        { g_t1[row] = p1; g_t2[row] = p2; }
    }
}

// ---------------- P3: global maxes of t2 and s2 ------------------------------
__global__ void max_kernel() {
    __shared__ float sm[512];
    int tid = threadIdx.x;   // 256
    float m1 = -1e30f, m2 = -1e30f;
    for (int i = tid; i < Nn; i += 256) {
        m1 = fmaxf(m1, g_t2[i]);
        m2 = fmaxf(m2, g_s2[i]);
    }
    sm[tid] = m1; sm[256 + tid] = m2;
    __syncthreads();
    for (int s = 128; s; s >>= 1) {
        if (tid < s) {
            sm[tid]       = fmaxf(sm[tid],       sm[tid + s]);
            sm[256 + tid] = fmaxf(sm[256 + tid], sm[256 + tid + s]);
        }
        __syncthreads();
    }
    if (tid == 0) { g_max2[0] = sm[0]; g_max2[1] = sm[256]; }
}

// ---------------- main fused attention pass (split-j partials) ---------------
// blockIdx.x = i-tile, blockIdx.y = side p, blockIdx.z = j-split s
__global__ void __launch_bounds__(128, 6)
attn_kernel(const int* __restrict__ adj) {
    int p = blockIdx.y;
    int sp = blockIdx.z;
    const float* xw = p ? g_xw_t : g_xw_s;
    const float* sv = p ? g_t1   : g_s1;
    const float* tv = p ? g_s2   : g_t2;
    float M = g_max2[p];
    int i0 = blockIdx.x * TI;
    int jbase = sp * JCH;

    __shared__ float s_wts[TI * (TJ + 1)];   // 16.25 KB
    __shared__ float s_x[TJ * Dd];           // 16 KB
    __shared__ float s_s[TI];
    __shared__ float s_m[TI];
    __shared__ float s_den[TI * 2];

    int tid = threadIdx.x;
    if (tid < TI) {
        float s = sv[i0 + tid];
        s_s[tid] = s;
        s_m[tid] = leaky(s + M);   // valid upper bound on row max (leaky monotone)
    }
    __syncthreads();

    int ig = tid >> 3;     // 0..15 : rows ig + 16r
    int dg = tid & 7;      // 0..7  : d pairs dg + 8c
    int fix = tid & 63;
    int half = tid >> 6;

    float sB = s_s[fix];
    float mB = s_m[fix];

    unsigned long long acc[4][4];
    #pragma unroll
    for (int r = 0; r < 4; r++)
        #pragma unroll
        for (int c = 0; c < 4; c++) acc[r][c] = 0ull;
    float denp = 0.f;

    for (int jt = 0; jt < JCH / TJ; jt++) {
        int j0 = jbase + jt * TJ;
        __syncthreads();

        // load xw tile [TJ x Dd] into smem
        {
            const float4* xt4 = (const float4*)(xw + j0 * Dd);
            float4* sx4 = (float4*)s_x;
            #pragma unroll
            for (int k = 0; k < 8; k++)
                sx4[tid + 128 * k] = xt4[tid + 128 * k];
        }

        // weight phase
        if (p == 0) {
            float tvA = __ldg(&tv[j0 + fix]);
            #pragma unroll 4
            for (int k = 0; k < 32; k++) {
                int ii = half + 2 * k;
                int av = adj[(size_t)(i0 + ii) * Nn + (j0 + fix)];
                float sc = leaky(s_s[ii] + tvA);
                float msk = (av > 0) ? 1.f : 0.f;
                s_wts[ii * (TJ + 1) + fix] = msk * __expf(sc - s_m[ii]);
            }
        } else {
            #pragma unroll 4
            for (int k = 0; k < 32; k++) {
                int jr = half + 2 * k;
                int av = adj[(size_t)(j0 + jr) * Nn + (i0 + fix)];
                float sc = leaky(sB + __ldg(&tv[j0 + jr]));
                float msk = (av > 0) ? 1.f : 0.f;
                s_wts[fix * (TJ + 1) + jr] = msk * __expf(sc - mB);
            }
        }
        __syncthreads();

        // accumulate with packed fp32x2
        const unsigned long long* sx2 = (const unsigned long long*)s_x;
        #pragma unroll 4
        for (int jj = 0; jj < TJ; jj++) {
            unsigned long long w2[4];
            #pragma unroll
            for (int r = 0; r < 4; r++) {
                float w = s_wts[(ig + 16 * r) * (TJ + 1) + jj];
                w2[r] = pack2(w, w);
            }
            #pragma unroll
            for (int c = 0; c < 4; c++) {
                unsigned long long xv = sx2[jj * 32 + dg + 8 * c];
                #pragma unroll
                for (int r = 0; r < 4; r++) ffma2(acc[r][c], w2[r], xv);
            }
        }

        // denominator partial over this tile
        {
            int ii = tid >> 1, h = tid & 1;
            const float* wr = &s_wts[ii * (TJ + 1) + h * 32];
            float ps = 0.f;
            #pragma unroll
            for (int u = 0; u < 32; u++) ps += wr[u];
            denp += ps;
        }
    }

    {
        int ii = tid >> 1, h = tid & 1;
        s_den[ii * 2 + h] = denp;
    }
    __syncthreads();

    // write partial den
    int buf = p * SPLITS + sp;
    if (tid < TI) {
        g_pden[(size_t)buf * Nn + i0 + tid] = s_den[tid * 2] + s_den[tid * 2 + 1];
    }

    // write partial num
    float* nump = g_pnum + (size_t)buf * Nn * Dd;
    #pragma unroll
    for (int r = 0; r < 4; r++) {
        int i = i0 + ig + 16 * r;
        #pragma unroll
        for (int c = 0; c < 4; c++) {
            float lo, hi;
            unpack2(acc[r][c], lo, hi);
            ((float2*)(nump + (size_t)i * Dd))[dg + 8 * c] = make_float2(lo, hi);
        }
    }
}

// ---------------- finish: sum partials, normalize, bias + ELU ----------------
__global__ void finish_kernel(const float* __restrict__ bs, const float* __restrict__ bt,
                              float* __restrict__ out) {
    int warp = threadIdx.x >> 5, lane = threadIdx.x & 31;
    int rg = blockIdx.x * 8 + warp;        // 0..16383
    int p = rg >> 13;
    int i = rg & (Nn - 1);
    const float* bias = p ? bt : bs;

    float2 acc = make_float2(0.f, 0.f);
    #pragma unroll
    for (int s = 0; s < SPLITS; s++) {
        const float2* np = (const float2*)(g_pnum + ((size_t)(p * SPLITS + s) * Nn + i) * Dd);
        float2 v = np[lane];
        acc.x += v.x; acc.y += v.y;
    }
    float den = (lane < SPLITS) ? g_pden[(size_t)(p * SPLITS + lane) * Nn + i] : 0.f;
    #pragma unroll
    for (int o = 16; o; o >>= 1) den += __shfl_xor_sync(0xffffffffu, den, o);
    float inv = 1.f / den;

    float v0 = acc.x * inv + bias[2 * lane];
    float v1 = acc.y * inv + bias[2 * lane + 1];
    v0 = (v0 > 0.f) ? v0 : expm1f(v0);
    v1 = (v1 > 0.f) ? v1 : expm1f(v1);
    ((float2*)(out + (size_t)rg * Dd))[lane] = make_float2(v0, v1);
}

// ---------------- launch ------------------------------------------------------
extern "C" void kernel_launch(void* const* d_in, const int* in_sizes, int n_in,
                              void* d_out, int out_size) {
    const float* xs  = (const float*)d_in[0];
    const float* xt  = (const float*)d_in[1];
    const int*   adj = (const int*)  d_in[2];
    const float* ws  = (const float*)d_in[3];
    const float* wt  = (const float*)d_in[4];
    const float* a   = (const float*)d_in[5];
    const float* bs  = (const float*)d_in[6];
    const float* bt  = (const float*)d_in[7];
    float* out = (float*)d_out;   // [2, 8192, 64]

    proj_kernel<<<dim3(Nn / 16, 2), 256>>>(xs, xt, ws, wt);
    proj_vec_kernel<<<dim3(Nn / 8, 2), 256>>>(a);
    max_kernel<<<1, 256>>>();
    attn_kernel<<<dim3(Nn / TI, 2, SPLITS), 128>>>(adj);
    finish_kernel<<<(2 * Nn) / 8, 256>>>(bs, bt, out);
}

// round 5
// speedup vs baseline: 2.5541x; 1.3501x over previous
#include <cuda_runtime.h>
#include <math.h>
#include <stdint.h>

#define Nn 8192
#define Dd 64
#define IN_F 128
#define TI 128
#define TJ 64
#define SPLITS 8
#define JCH (Nn / SPLITS)     // 1024
#define NTILE (JCH / TJ)      // 16
#define LOG2E 1.4426950408889634f

// dynamic smem layout: s_sm embedded so TOTAL = one dynamic block (needs opt-in)
#define OFF_SSM 0
#define OFF_AHI 1024
#define OFF_ALO 17408
#define OFF_BHI 33792
#define OFF_BLO 41984
#define DSMEM   50176

// ---------------- device scratch ---------------------------------------------
__device__ float g_xw_s[Nn * Dd];
__device__ float g_xw_t[Nn * Dd];
__device__ float g_s1[Nn], g_s2[Nn], g_t1[Nn], g_t2[Nn];   // pre-scaled by log2e
__device__ float g_max2[2];
__device__ unsigned short g_xT_hi[2][Dd * Nn];   // [side][d][j]
__device__ unsigned short g_xT_lo[2][Dd * Nn];
__device__ float g_pnum[2 * SPLITS * Nn * Dd];
__device__ float g_pden[2 * SPLITS * Nn];

// ---------------- helpers -----------------------------------------------------
__device__ __forceinline__ uint32_t smem_u32(const void* p) {
    uint32_t a;
    asm("{ .reg .u64 t; cvta.to.shared.u64 t, %1; cvt.u32.u64 %0, t; }" : "=r"(a) : "l"(p));
    return a;
}
__device__ __forceinline__ float leaky(float z) { return fmaxf(z, 0.01f * z); }
__device__ __forceinline__ float ex2(float x) {
    float r; asm("ex2.approx.f32 %0, %1;" : "=f"(r) : "f"(x)); return r;
}
// pack {lo=w0, hi=w1} as bf16x2
__device__ __forceinline__ uint32_t bfpack(float w0, float w1) {
    uint32_t r; asm("cvt.rn.bf16x2.f32 %0, %1, %2;" : "=r"(r) : "f"(w1), "f"(w0)); return r;
}
__device__ __forceinline__ void split_bf16(float v, unsigned short& hi, unsigned short& lo) {
    asm("cvt.rn.bf16.f32 %0, %1;" : "=h"(hi) : "f"(v));
    float hf = __uint_as_float(((uint32_t)hi) << 16);
    float r = v - hf;
    asm("cvt.rn.bf16.f32 %0, %1;" : "=h"(lo) : "f"(r));
}
__device__ __forceinline__ void ldsm4(uint32_t* r, uint32_t addr) {
    asm volatile("ldmatrix.sync.aligned.m8n8.x4.shared.b16 {%0,%1,%2,%3}, [%4];"
        : "=r"(r[0]), "=r"(r[1]), "=r"(r[2]), "=r"(r[3]) : "r"(addr));
}
__device__ __forceinline__ void mma16816(float* d, const uint32_t* a, uint32_t b0, uint32_t b1) {
    asm volatile(
        "mma.sync.aligned.m16n8k16.row.col.f32.bf16.bf16.f32 "
        "{%0,%1,%2,%3},{%4,%5,%6,%7},{%8,%9},{%0,%1,%2,%3};"
        : "+f"(d[0]), "+f"(d[1]), "+f"(d[2]), "+f"(d[3])
        : "r"(a[0]), "r"(a[1]), "r"(a[2]), "r"(a[3]), "r"(b0), "r"(b1));
}

// ---------------- P1: xw = x @ W, plus transposed bf16 hi/lo planes ----------
__global__ void proj_kernel(const float* __restrict__ xs, const float* __restrict__ xt,
                            const float* __restrict__ ws, const float* __restrict__ wt) {
    int y = blockIdx.y;
    const float* x = y ? xt : xs;
    const float* W = y ? wt : ws;
    float* out = y ? g_xw_t : g_xw_s;

    __shared__ float Wsm[IN_F * Dd];
    __shared__ float xsm[16 * IN_F];

    int tid = threadIdx.x;
    const float4* W4 = (const float4*)W;
    float4* Ws4 = (float4*)Wsm;
    for (int k = tid; k < IN_F * Dd / 4; k += 256) Ws4[k] = W4[k];

    int r0 = blockIdx.x * 16;
    const float4* x4 = (const float4*)(x + r0 * IN_F);
    float4* xs4 = (float4*)xsm;
    for (int k = tid; k < 16 * IN_F / 4; k += 256) xs4[k] = x4[k];
    __syncthreads();

    int c = tid & 63, rq = tid >> 6;
    float acc[4] = {0.f, 0.f, 0.f, 0.f};
    #pragma unroll 4
    for (int kk = 0; kk < IN_F; kk++) {
        float wv = Wsm[kk * Dd + c];
        #pragma unroll
        for (int k = 0; k < 4; k++)
            acc[k] += xsm[(rq + 4 * k) * IN_F + kk] * wv;
    }
    #pragma unroll
    for (int k = 0; k < 4; k++) {
        int row = r0 + rq + 4 * k;
        float v = acc[k];
        out[row * Dd + c] = v;
        unsigned short hi, lo;
        split_bf16(v, hi, lo);
        g_xT_hi[y][(size_t)c * Nn + row] = hi;
        g_xT_lo[y][(size_t)c * Nn + row] = lo;
    }
}

// ---------------- P2: projections onto a1/a2, PRE-SCALED by log2e -----------
__global__ void proj_vec_kernel(const float* __restrict__ a) {
    int y = blockIdx.y;
    const float* xw = y ? g_xw_t : g_xw_s;
    int w = threadIdx.x >> 5, lane = threadIdx.x & 31;
    int row = blockIdx.x * 8 + w;
    float v0 = xw[row * Dd + lane];
    float v1 = xw[row * Dd + 32 + lane];
    float p1 = v0 * a[lane] + v1 * a[32 + lane];
    float p2 = v0 * a[64 + lane] + v1 * a[96 + lane];
    #pragma unroll
    for (int o = 16; o; o >>= 1) {
        p1 += __shfl_down_sync(0xffffffffu, p1, o);
        p2 += __shfl_down_sync(0xffffffffu, p2, o);
    }
    if (lane == 0) {
        p1 *= LOG2E; p2 *= LOG2E;   // leaky(c*z)=c*leaky(z) for c>0, so scaling commutes
        if (y == 0) { g_s1[row] = p1; g_s2[row] = p2; }
        else        { g_t1[row] = p1; g_t2[row] = p2; }
    }
}

// ---------------- P3: maxes ---------------------------------------------------
__global__ void max_kernel() {
    __shared__ float sm[512];
    int tid = threadIdx.x;
    float m1 = -1e30f, m2 = -1e30f;
    for (int i = tid; i < Nn; i += 256) {
        m1 = fmaxf(m1, g_t2[i]);
        m2 = fmaxf(m2, g_s2[i]);
    }
    sm[tid] = m1; sm[256 + tid] = m2;
    __syncthreads();
    for (int s = 128; s; s >>= 1) {
        if (tid < s) {
            sm[tid]       = fmaxf(sm[tid],       sm[tid + s]);
            sm[256 + tid] = fmaxf(sm[256 + tid], sm[256 + tid + s]);
        }
        __syncthreads();
    }
    if (tid == 0) { g_max2[0] = sm[0]; g_max2[1] = sm[256]; }
}

// ---------------- main attention: mma.sync bf16 hi/lo ------------------------
__global__ void __launch_bounds__(256, 3)
attn_kernel(const int* __restrict__ adj) {
    extern __shared__ char smc[];
    uint32_t smb = smem_u32(smc);
    float2* s_sm = (float2*)(smc + OFF_SSM);   // (s', m') pre-scaled, in dynamic smem

    int p = blockIdx.y, sp = blockIdx.z;
    int i0 = blockIdx.x * TI;
    int jbase = sp * JCH;
    const float* sv = p ? g_t1 : g_s1;
    const float* tv = p ? g_s2 : g_t2;
    const unsigned short* XH = g_xT_hi[p];
    const unsigned short* XL = g_xT_lo[p];
    float M = g_max2[p];

    int tid = threadIdx.x, wid = tid >> 5, lane = tid & 31;

    if (tid < TI) {
        float s = sv[i0 + tid];
        s_sm[tid] = make_float2(s, leaky(s + M));
    }
    __syncthreads();

    // ldmatrix per-thread address components (XOR swizzle: col ^ ((row&7)<<4))
    uint32_t aRow = wid * 16 + (lane & 7) + ((lane >> 3) & 1) * 8;
    uint32_t aSel = ((lane >> 4) & 1) * 16;
    uint32_t aSwz = (aRow & 7) << 4;
    uint32_t aBase = smb + aRow * 128;
    uint32_t bRow = (lane & 7) + ((lane >> 4) & 1) * 8;
    uint32_t bSel = ((lane >> 3) & 1) * 16;
    uint32_t bSwz = (lane & 7) << 4;
    uint32_t bBase = smb + bRow * 128;

    const uint32_t ONE2 = 0x3F803F80u;   // bf16x2 {1.0, 1.0}

    float acc[8][4];
    float den[4];
    #pragma unroll
    for (int n = 0; n < 8; n++)
        #pragma unroll
        for (int q = 0; q < 4; q++) acc[n][q] = 0.f;
    #pragma unroll
    for (int q = 0; q < 4; q++) den[q] = 0.f;

    // staging indices for B (xw^T)
    int sd = tid >> 2, scc = tid & 3;
    uint32_t sSwz = (sd & 7) << 4;
    uint32_t sRow = sd * 128;

    for (int jt = 0; jt < NTILE; jt++) {
        int j0 = jbase + jt * TJ;

        // ---- stage B tile: xw^T hi/lo [64 d x 64 j] ----
        {
            const uint4* srch = (const uint4*)(XH + (size_t)sd * Nn + j0);
            const uint4* srcl = (const uint4*)(XL + (size_t)sd * Nn + j0);
            *(uint4*)(smc + OFF_BHI + sRow + ((scc * 16) ^ sSwz))       = srch[scc];
            *(uint4*)(smc + OFF_BHI + sRow + (((scc + 4) * 16) ^ sSwz)) = srch[scc + 4];
            *(uint4*)(smc + OFF_BLO + sRow + ((scc * 16) ^ sSwz))       = srcl[scc];
            *(uint4*)(smc + OFF_BLO + sRow + (((scc + 4) * 16) ^ sSwz)) = srcl[scc + 4];
        }

        // ---- weight phase: A hi/lo [128 i x 64 j] ----
        if (p == 0) {
            int jp = lane * 2;
            float2 tvv = __ldg((const float2*)(tv + j0 + jp));
            const int2* aptr = (const int2*)(adj + (size_t)(i0 + wid * 16) * Nn + j0) + lane;
            #pragma unroll 4
            for (int k = 0; k < 16; k++) {
                int il = wid * 16 + k;
                float2 sm2 = s_sm[il];
                int2 av = aptr[(size_t)k * (Nn / 2)];
                float z0 = sm2.x + tvv.x, z1 = sm2.x + tvv.y;
                float w0 = ex2(fmaxf(z0, 0.01f * z0) - sm2.y);
                float w1 = ex2(fmaxf(z1, 0.01f * z1) - sm2.y);
                if (av.x <= 0) w0 = 0.f;
                if (av.y <= 0) w1 = 0.f;
                uint32_t hi = bfpack(w0, w1);
                float h0 = __uint_as_float(hi << 16);
                float h1 = __uint_as_float(hi & 0xFFFF0000u);
                uint32_t lo = bfpack(w0 - h0, w1 - h1);
                uint32_t off = il * 128 + ((jp * 2) ^ ((il & 7) << 4));
                *(uint32_t*)(smc + OFF_AHI + off) = hi;
                *(uint32_t*)(smc + OFF_ALO + off) = lo;
            }
        } else {
            int ip = (tid & 63) * 2;
            int jq = tid >> 6;
            float2 sa = s_sm[ip], sb = s_sm[ip + 1];
            const int2* aptr = (const int2*)(adj + (size_t)(j0 + jq * 16) * Nn + i0 + ip);
            #pragma unroll 4
            for (int k = 0; k < 16; k++) {
                int jr = jq * 16 + k;
                float tvj = __ldg(tv + j0 + jr);
                int2 av = aptr[(size_t)k * (Nn / 2)];
                float z0 = sa.x + tvj, z1 = sb.x + tvj;
                float w0 = ex2(fmaxf(z0, 0.01f * z0) - sa.y);
                float w1 = ex2(fmaxf(z1, 0.01f * z1) - sb.y);
                if (av.x <= 0) w0 = 0.f;
                if (av.y <= 0) w1 = 0.f;
                unsigned short h0, l0, h1, l1;
                split_bf16(w0, h0, l0);
                split_bf16(w1, h1, l1);
                uint32_t c0 = ip * 128 + ((jr * 2) ^ ((ip & 7) << 4));
                uint32_t c1 = (ip + 1) * 128 + ((jr * 2) ^ (((ip + 1) & 7) << 4));
                *(unsigned short*)(smc + OFF_AHI + c0) = h0;
                *(unsigned short*)(smc + OFF_ALO + c0) = l0;
                *(unsigned short*)(smc + OFF_AHI + c1) = h1;
                *(unsigned short*)(smc + OFF_ALO + c1) = l1;
            }
        }
        __syncthreads();

        // ---- mma phase ----
        #pragma unroll
        for (int k = 0; k < 4; k++) {
            uint32_t ah[4], al[4];
            ldsm4(ah, aBase + OFF_AHI + ((aSel + 32 * k) ^ aSwz));
            ldsm4(al, aBase + OFF_ALO + ((aSel + 32 * k) ^ aSwz));
            mma16816(den, ah, ONE2, ONE2);
            mma16816(den, al, ONE2, ONE2);
            #pragma unroll
            for (int nn = 0; nn < 4; nn++) {
                uint32_t bh[4], bl[4];
                uint32_t boff = nn * 2048 + ((bSel + 32 * k) ^ bSwz);
                ldsm4(bh, bBase + OFF_BHI + boff);
                ldsm4(bl, bBase + OFF_BLO + boff);
                mma16816(acc[2 * nn],     ah, bh[0], bh[1]);
                mma16816(acc[2 * nn + 1], ah, bh[2], bh[3]);
                mma16816(acc[2 * nn],     ah, bl[0], bl[1]);
                mma16816(acc[2 * nn + 1], ah, bl[2], bl[3]);
                mma16816(acc[2 * nn],     al, bh[0], bh[1]);
                mma16816(acc[2 * nn + 1], al, bh[2], bh[3]);
            }
        }
        __syncthreads();
    }

    // ---- write partials ----
    int buf = p * SPLITS + sp;
    int g = lane >> 2, tg = lane & 3;
    float* nump = g_pnum + (size_t)buf * Nn * Dd;
    int ia = i0 + wid * 16 + g;
    int ib = ia + 8;
    #pragma unroll
    for (int n = 0; n < 8; n++) {
        int col = n * 8 + tg * 2;
        *(float2*)(nump + (size_t)ia * Dd + col) = make_float2(acc[n][0], acc[n][1]);
        *(float2*)(nump + (size_t)ib * Dd + col) = make_float2(acc[n][2], acc[n][3]);
    }
    if (tg == 0) {
        g_pden[(size_t)buf * Nn + ia] = den[0];
        g_pden[(size_t)buf * Nn + ib] = den[2];
    }
}

// ---------------- finish: sum partials, normalize, bias + ELU ----------------
__global__ void finish_kernel(const float* __restrict__ bs, const float* __restrict__ bt,
                              float* __restrict__ out) {
    int warp = threadIdx.x >> 5, lane = threadIdx.x & 31;
    int rg = blockIdx.x * 8 + warp;
    int p = rg >> 13;
    int i = rg & (Nn - 1);
    const float* bias = p ? bt : bs;

    float2 acc = make_float2(0.f, 0.f);
    #pragma unroll
    for (int s = 0; s < SPLITS; s++) {
        const float2* np = (const float2*)(g_pnum + ((size_t)(p * SPLITS + s) * Nn + i) * Dd);
        float2 v = np[lane];
        acc.x += v.x; acc.y += v.y;
    }
    float den = (lane < SPLITS) ? g_pden[(size_t)(p * SPLITS + lane) * Nn + i] : 0.f;
    #pragma unroll
    for (int o = 16; o; o >>= 1) den += __shfl_xor_sync(0xffffffffu, den, o);
    float inv = 1.f / den;

    float v0 = acc.x * inv + bias[2 * lane];
    float v1 = acc.y * inv + bias[2 * lane + 1];
    v0 = (v0 > 0.f) ? v0 : expm1f(v0);
    v1 = (v1 > 0.f) ? v1 : expm1f(v1);
    ((float2*)(out + (size_t)rg * Dd))[lane] = make_float2(v0, v1);
}

// ---------------- launch ------------------------------------------------------
extern "C" void kernel_launch(void* const* d_in, const int* in_sizes, int n_in,
                              void* d_out, int out_size) {
    const float* xs  = (const float*)d_in[0];
    const float* xt  = (const float*)d_in[1];
    const int*   adj = (const int*)  d_in[2];
    const float* ws  = (const float*)d_in[3];
    const float* wt  = (const float*)d_in[4];
    const float* a   = (const float*)d_in[5];
    const float* bs  = (const float*)d_in[6];
    const float* bt  = (const float*)d_in[7];
    float* out = (float*)d_out;   // [2, 8192, 64]

    // Function-attribute call (not a stream op; legal under graph capture,
    // idempotent and deterministic). Needed: 50176 B dynamic smem > 48 KB default.
    cudaFuncSetAttribute(attn_kernel, cudaFuncAttributeMaxDynamicSharedMemorySize, DSMEM);

    proj_kernel<<<dim3(Nn / 16, 2), 256>>>(xs, xt, ws, wt);
    proj_vec_kernel<<<dim3(Nn / 8, 2), 256>>>(a);
    max_kernel<<<1, 256>>>();
    attn_kernel<<<dim3(Nn / TI, 2, SPLITS), 256, DSMEM>>>(adj);
    finish_kernel<<<(2 * Nn) / 8, 256>>>(bs, bt, out);
}

// round 6
// speedup vs baseline: 3.0430x; 1.1914x over previous
#include <cuda_runtime.h>
#include <math.h>
#include <stdint.h>

#define Nn 8192
#define Dd 64
#define IN_F 128
#define TI 128
#define TJ 64
#define SPLITS 8
#define JCH (Nn / SPLITS)     // 1024
#define NTILE (JCH / TJ)      // 16
#define LOG2E 1.4426950408889634f

// ---------------- device scratch ---------------------------------------------
__device__ float g_xw_s[Nn * Dd];
__device__ float g_xw_t[Nn * Dd];
__device__ float g_s1[Nn], g_s2[Nn], g_t1[Nn], g_t2[Nn];   // pre-scaled by log2e
__device__ float g_max2[2];
__device__ unsigned short g_xT_hi[2][Dd * Nn];   // [side][d][j]
__device__ unsigned short g_xT_lo[2][Dd * Nn];
__device__ float g_pnum[2 * SPLITS * Nn * Dd];
__device__ float g_pden[2 * SPLITS * Nn];

// ---------------- helpers -----------------------------------------------------
__device__ __forceinline__ uint32_t smem_u32(const void* p) {
    uint32_t a;
    asm("{ .reg .u64 t; cvta.to.shared.u64 t, %1; cvt.u32.u64 %0, t; }" : "=r"(a) : "l"(p));
    return a;
}
__device__ __forceinline__ float leaky(float z) { return fmaxf(z, 0.01f * z); }
__device__ __forceinline__ float ex2(float x) {
    float r; asm("ex2.approx.f32 %0, %1;" : "=f"(r) : "f"(x)); return r;
}
// pack {lo half = w0, hi half = w1} as bf16x2
__device__ __forceinline__ uint32_t bfpack(float w0, float w1) {
    uint32_t r; asm("cvt.rn.bf16x2.f32 %0, %1, %2;" : "=r"(r) : "f"(w1), "f"(w0)); return r;
}
__device__ __forceinline__ void split_bf16(float v, unsigned short& hi, unsigned short& lo) {
    asm("cvt.rn.bf16.f32 %0, %1;" : "=h"(hi) : "f"(v));
    float hf = __uint_as_float(((uint32_t)hi) << 16);
    float r = v - hf;
    asm("cvt.rn.bf16.f32 %0, %1;" : "=h"(lo) : "f"(r));
}
__device__ __forceinline__ void ldsm4(uint32_t* r, uint32_t addr) {
    asm volatile("ldmatrix.sync.aligned.m8n8.x4.shared.b16 {%0,%1,%2,%3}, [%4];"
        : "=r"(r[0]), "=r"(r[1]), "=r"(r[2]), "=r"(r[3]) : "r"(addr));
}
__device__ __forceinline__ void mma16816(float* d, const uint32_t* a, uint32_t b0, uint32_t b1) {
    asm volatile(
        "mma.sync.aligned.m16n8k16.row.col.f32.bf16.bf16.f32 "
        "{%0,%1,%2,%3},{%4,%5,%6,%7},{%8,%9},{%0,%1,%2,%3};"
        : "+f"(d[0]), "+f"(d[1]), "+f"(d[2]), "+f"(d[3])
        : "r"(a[0]), "r"(a[1]), "r"(a[2]), "r"(a[3]), "r"(b0), "r"(b1));
}
// masked softmax weight (log2-domain inputs)
__device__ __forceinline__ float wgen(float s, float m, float t, int av) {
    float z = s + t;
    float w = ex2(fmaxf(z, 0.01f * z) - m);
    return (av > 0) ? w : 0.f;
}

// ---------------- P1: xw = x @ W, plus transposed bf16 hi/lo planes ----------
__global__ void proj_kernel(const float* __restrict__ xs, const float* __restrict__ xt,
                            const float* __restrict__ ws, const float* __restrict__ wt) {
    int y = blockIdx.y;
    const float* x = y ? xt : xs;
    const float* W = y ? wt : ws;
    float* out = y ? g_xw_t : g_xw_s;

    __shared__ float Wsm[IN_F * Dd];
    __shared__ float xsm[16 * IN_F];

    int tid = threadIdx.x;
    const float4* W4 = (const float4*)W;
    float4* Ws4 = (float4*)Wsm;
    for (int k = tid; k < IN_F * Dd / 4; k += 256) Ws4[k] = W4[k];

    int r0 = blockIdx.x * 16;
    const float4* x4 = (const float4*)(x + r0 * IN_F);
    float4* xs4 = (float4*)xsm;
    for (int k = tid; k < 16 * IN_F / 4; k += 256) xs4[k] = x4[k];
    __syncthreads();

    int c = tid & 63, rq = tid >> 6;
    float acc[4] = {0.f, 0.f, 0.f, 0.f};
    #pragma unroll 4
    for (int kk = 0; kk < IN_F; kk++) {
        float wv = Wsm[kk * Dd + c];
        #pragma unroll
        for (int k = 0; k < 4; k++)
            acc[k] += xsm[(rq + 4 * k) * IN_F + kk] * wv;
    }
    #pragma unroll
    for (int k = 0; k < 4; k++) {
        int row = r0 + rq + 4 * k;
        float v = acc[k];
        out[row * Dd + c] = v;
        unsigned short hi, lo;
        split_bf16(v, hi, lo);
        g_xT_hi[y][(size_t)c * Nn + row] = hi;
        g_xT_lo[y][(size_t)c * Nn + row] = lo;
    }
}

// ---------------- P2: projections onto a1/a2, PRE-SCALED by log2e -----------
__global__ void proj_vec_kernel(const float* __restrict__ a) {
    int y = blockIdx.y;
    const float* xw = y ? g_xw_t : g_xw_s;
    int w = threadIdx.x >> 5, lane = threadIdx.x & 31;
    int row = blockIdx.x * 8 + w;
    float v0 = xw[row * Dd + lane];
    float v1 = xw[row * Dd + 32 + lane];
    float p1 = v0 * a[lane] + v1 * a[32 + lane];
    float p2 = v0 * a[64 + lane] + v1 * a[96 + lane];
    #pragma unroll
    for (int o = 16; o; o >>= 1) {
        p1 += __shfl_down_sync(0xffffffffu, p1, o);
        p2 += __shfl_down_sync(0xffffffffu, p2, o);
    }
    if (lane == 0) {
        p1 *= LOG2E; p2 *= LOG2E;   // leaky(c*z)=c*leaky(z) for c>0
        if (y == 0) { g_s1[row] = p1; g_s2[row] = p2; }
        else        { g_t1[row] = p1; g_t2[row] = p2; }
    }
}

// ---------------- P3: maxes ---------------------------------------------------
__global__ void max_kernel() {
    __shared__ float sm[512];
    int tid = threadIdx.x;
    float m1 = -1e30f, m2 = -1e30f;
    for (int i = tid; i < Nn; i += 256) {
        m1 = fmaxf(m1, g_t2[i]);
        m2 = fmaxf(m2, g_s2[i]);
    }
    sm[tid] = m1; sm[256 + tid] = m2;
    __syncthreads();
    for (int s = 128; s; s >>= 1) {
        if (tid < s) {
            sm[tid]       = fmaxf(sm[tid],       sm[tid + s]);
            sm[256 + tid] = fmaxf(sm[256 + tid], sm[256 + tid + s]);
        }
        __syncthreads();
    }
    if (tid == 0) { g_max2[0] = sm[0]; g_max2[1] = sm[256]; }
}

// ---------------- main attention: A-fragments generated in registers ---------
__global__ void __launch_bounds__(256, 2)
attn_kernel(const int* __restrict__ adj) {
    __shared__ __align__(16) char smc[16384];   // B hi [0,8K), B lo [8K,16K)
    uint32_t smb = smem_u32(smc);

    int p = blockIdx.y, sp = blockIdx.z;
    int i0 = blockIdx.x * TI;
    int jbase = sp * JCH;
    const float* sv = p ? g_t1 : g_s1;
    const float* tv = p ? g_s2 : g_t2;
    const unsigned short* XH = g_xT_hi[p];
    const unsigned short* XL = g_xT_lo[p];
    float M = g_max2[p];

    int tid = threadIdx.x, wid = tid >> 5, lane = tid & 31;
    int r = lane >> 2, c = lane & 3;
    int iA = i0 + wid * 16 + r;    // rows this thread's A frags cover
    int iB = iA + 8;

    float sA = sv[iA], sB = sv[iB];
    float mA = leaky(sA + M), mB = leaky(sB + M);

    // B ldmatrix addressing (proven layout from round 5)
    uint32_t bRow = (lane & 7) + ((lane >> 4) & 1) * 8;
    uint32_t bSel = ((lane >> 3) & 1) * 16;
    uint32_t bSwz = (lane & 7) << 4;
    uint32_t bBase = smb + bRow * 128;

    // B staging indices
    int sd = tid >> 2, scc = tid & 3;
    uint32_t sSwz = (sd & 7) << 4;
    uint32_t sRow = sd * 128;

    const uint32_t ONE2 = 0x3F803F80u;   // bf16x2 {1.0, 1.0}

    float acc[8][4];
    float den[4];
    #pragma unroll
    for (int n = 0; n < 8; n++)
        #pragma unroll
        for (int q = 0; q < 4; q++) acc[n][q] = 0.f;
    #pragma unroll
    for (int q = 0; q < 4; q++) den[q] = 0.f;

    for (int jt = 0; jt < NTILE; jt++) {
        int j0 = jbase + jt * TJ;

        // ---- adjacency preload for the whole tile (A-fragment positions) ----
        // avv[8k+{0..3}] = (rowA, j=jc,jc+1,jc+8,jc+9); [8k+{4..7}] = rowB same cols
        int avv[32];
        if (p == 0) {
            const int* rowA = adj + (size_t)iA * Nn + j0 + 2 * c;
            const int* rowB = adj + (size_t)iB * Nn + j0 + 2 * c;
            #pragma unroll
            for (int k = 0; k < 4; k++) {
                int2 a0 = *(const int2*)(rowA + 16 * k);
                int2 a1 = *(const int2*)(rowA + 16 * k + 8);
                int2 b0 = *(const int2*)(rowB + 16 * k);
                int2 b1 = *(const int2*)(rowB + 16 * k + 8);
                avv[8 * k + 0] = a0.x; avv[8 * k + 1] = a0.y;
                avv[8 * k + 2] = a1.x; avv[8 * k + 3] = a1.y;
                avv[8 * k + 4] = b0.x; avv[8 * k + 5] = b0.y;
                avv[8 * k + 6] = b1.x; avv[8 * k + 7] = b1.y;
            }
        } else {
            #pragma unroll
            for (int k = 0; k < 4; k++) {
                int jc = j0 + 16 * k + 2 * c;
                const int* c1 = adj + (size_t)jc * Nn;
                const int* c2 = adj + (size_t)(jc + 1) * Nn;
                const int* c3 = adj + (size_t)(jc + 8) * Nn;
                const int* c4 = adj + (size_t)(jc + 9) * Nn;
                avv[8 * k + 0] = c1[iA]; avv[8 * k + 1] = c2[iA];
                avv[8 * k + 2] = c3[iA]; avv[8 * k + 3] = c4[iA];
                avv[8 * k + 4] = c1[iB]; avv[8 * k + 5] = c2[iB];
                avv[8 * k + 6] = c3[iB]; avv[8 * k + 7] = c4[iB];
            }
        }

        // ---- stage B tile: xw^T hi/lo [64 d x 64 j] (overlaps adj loads) ----
        {
            const uint4* srch = (const uint4*)(XH + (size_t)sd * Nn + j0);
            const uint4* srcl = (const uint4*)(XL + (size_t)sd * Nn + j0);
            *(uint4*)(smc + sRow + ((scc * 16) ^ sSwz))              = srch[scc];
            *(uint4*)(smc + sRow + (((scc + 4) * 16) ^ sSwz))        = srch[scc + 4];
            *(uint4*)(smc + 8192 + sRow + ((scc * 16) ^ sSwz))       = srcl[scc];
            *(uint4*)(smc + 8192 + sRow + (((scc + 4) * 16) ^ sSwz)) = srcl[scc + 4];
        }
        __syncthreads();

        // ---- per K-chunk: build A frags in registers, mma ----
        #pragma unroll
        for (int k = 0; k < 4; k++) {
            int jc = j0 + 16 * k + 2 * c;
            float2 t12 = *(const float2*)(tv + jc);
            float2 t34 = *(const float2*)(tv + jc + 8);

            float w0 = wgen(sA, mA, t12.x, avv[8 * k + 0]);
            float w1 = wgen(sA, mA, t12.y, avv[8 * k + 1]);
            float w2 = wgen(sA, mA, t34.x, avv[8 * k + 2]);
            float w3 = wgen(sA, mA, t34.y, avv[8 * k + 3]);
            float w4 = wgen(sB, mB, t12.x, avv[8 * k + 4]);
            float w5 = wgen(sB, mB, t12.y, avv[8 * k + 5]);
            float w6 = wgen(sB, mB, t34.x, avv[8 * k + 6]);
            float w7 = wgen(sB, mB, t34.y, avv[8 * k + 7]);

            uint32_t ah[4], al[4];
            ah[0] = bfpack(w0, w1);   // a0: (row r,   k 2c..2c+1)
            ah[1] = bfpack(w4, w5);   // a1: (row r+8, k 2c..2c+1)
            ah[2] = bfpack(w2, w3);   // a2: (row r,   k 2c+8..)
            ah[3] = bfpack(w6, w7);   // a3: (row r+8, k 2c+8..)
            {
                float h;
                h = __uint_as_float(ah[0] << 16);          float e0 = w0 - h;
                h = __uint_as_float(ah[0] & 0xFFFF0000u);  float e1 = w1 - h;
                al[0] = bfpack(e0, e1);
                h = __uint_as_float(ah[1] << 16);          e0 = w4 - h;
                h = __uint_as_float(ah[1] & 0xFFFF0000u);  e1 = w5 - h;
                al[1] = bfpack(e0, e1);
                h = __uint_as_float(ah[2] << 16);          e0 = w2 - h;
                h = __uint_as_float(ah[2] & 0xFFFF0000u);  e1 = w3 - h;
                al[2] = bfpack(e0, e1);
                h = __uint_as_float(ah[3] << 16);          e0 = w6 - h;
                h = __uint_as_float(ah[3] & 0xFFFF0000u);  e1 = w7 - h;
                al[3] = bfpack(e0, e1);
            }

            // denominator: ones-B
            mma16816(den, ah, ONE2, ONE2);
            mma16816(den, al, ONE2, ONE2);

            #pragma unroll
            for (int nn = 0; nn < 4; nn++) {
                uint32_t bh[4], bl[4];
                uint32_t boff = nn * 2048 + ((bSel + 32 * k) ^ bSwz);
                ldsm4(bh, bBase + boff);
                ldsm4(bl, bBase + 8192 + boff);
                mma16816(acc[2 * nn],     ah, bh[0], bh[1]);
                mma16816(acc[2 * nn + 1], ah, bh[2], bh[3]);
                mma16816(acc[2 * nn],     ah, bl[0], bl[1]);
                mma16816(acc[2 * nn + 1], ah, bl[2], bl[3]);
                mma16816(acc[2 * nn],     al, bh[0], bh[1]);
                mma16816(acc[2 * nn + 1], al, bh[2], bh[3]);
            }
        }
        __syncthreads();
    }

    // ---- write partials ----
    int buf = p * SPLITS + sp;
    int tg = lane & 3;
    float* nump = g_pnum + (size_t)buf * Nn * Dd;
    #pragma unroll
    for (int n = 0; n < 8; n++) {
        int col = n * 8 + tg * 2;
        *(float2*)(nump + (size_t)iA * Dd + col) = make_float2(acc[n][0], acc[n][1]);
        *(float2*)(nump + (size_t)iB * Dd + col) = make_float2(acc[n][2], acc[n][3]);
    }
    if (tg == 0) {
        g_pden[(size_t)buf * Nn + iA] = den[0];
        g_pden[(size_t)buf * Nn + iB] = den[2];
    }
}

// ---------------- finish: sum partials, normalize, bias + ELU ----------------
__global__ void finish_kernel(const float* __restrict__ bs, const float* __restrict__ bt,
                              float* __restrict__ out) {
    int warp = threadIdx.x >> 5, lane = threadIdx.x & 31;
    int rg = blockIdx.x * 8 + warp;
    int p = rg >> 13;
    int i = rg & (Nn - 1);
    const float* bias = p ? bt : bs;

    float2 acc = make_float2(0.f, 0.f);
    #pragma unroll
    for (int s = 0; s < SPLITS; s++) {
        const float2* np = (const float2*)(g_pnum + ((size_t)(p * SPLITS + s) * Nn + i) * Dd);
        float2 v = np[lane];
        acc.x += v.x; acc.y += v.y;
    }
    float den = (lane < SPLITS) ? g_pden[(size_t)(p * SPLITS + lane) * Nn + i] : 0.f;
    #pragma unroll
    for (int o = 16; o; o >>= 1) den += __shfl_xor_sync(0xffffffffu, den, o);
    float inv = 1.f / den;

    float v0 = acc.x * inv + bias[2 * lane];
    float v1 = acc.y * inv + bias[2 * lane + 1];
    v0 = (v0 > 0.f) ? v0 : expm1f(v0);
    v1 = (v1 > 0.f) ? v1 : expm1f(v1);
    ((float2*)(out + (size_t)rg * Dd))[lane] = make_float2(v0, v1);
}

// ---------------- launch ------------------------------------------------------
extern "C" void kernel_launch(void* const* d_in, const int* in_sizes, int n_in,
                              void* d_out, int out_size) {
    const float* xs  = (const float*)d_in[0];
    const float* xt  = (const float*)d_in[1];
    const int*   adj = (const int*)  d_in[2];
    const float* ws  = (const float*)d_in[3];
    const float* wt  = (const float*)d_in[4];
    const float* a   = (const float*)d_in[5];
    const float* bs  = (const float*)d_in[6];
    const float* bt  = (const float*)d_in[7];
    float* out = (float*)d_out;   // [2, 8192, 64]

    proj_kernel<<<dim3(Nn / 16, 2), 256>>>(xs, xt, ws, wt);
    proj_vec_kernel<<<dim3(Nn / 8, 2), 256>>>(a);
    max_kernel<<<1, 256>>>();
    attn_kernel<<<dim3(Nn / TI, 2, SPLITS), 256>>>(adj);
    finish_kernel<<<(2 * Nn) / 8, 256>>>(bs, bt, out);
}

// round 8
// speedup vs baseline: 3.1673x; 1.0408x over previous
#include <cuda_runtime.h>
#include <math.h>
#include <stdint.h>

#define Nn 8192
#define Dd 64
#define IN_F 128
#define TI 128
#define TJ 64
#define SPLITS 8
#define JCH (Nn / SPLITS)     // 1024
#define NTILE (JCH / TJ)      // 16
#define LOG2E 1.4426950408889634f

// ---------------- device scratch ---------------------------------------------
__device__ float g_xw_s[Nn * Dd];
__device__ float g_xw_t[Nn * Dd];
__device__ float g_s1[Nn], g_s2[Nn], g_t1[Nn], g_t2[Nn];   // pre-scaled by log2e
__device__ float g_max2[2];
__device__ unsigned short g_xT_hi[2][Dd * Nn];   // [side][d][j]
__device__ unsigned short g_xT_lo[2][Dd * Nn];
__device__ float g_pnum[2 * SPLITS * Nn * Dd];
__device__ float g_pden[2 * SPLITS * Nn];

// ---------------- helpers -----------------------------------------------------
__device__ __forceinline__ uint32_t smem_u32(const void* p) {
    uint32_t a;
    asm("{ .reg .u64 t; cvta.to.shared.u64 t, %1; cvt.u32.u64 %0, t; }" : "=r"(a) : "l"(p));
    return a;
}
__device__ __forceinline__ float leaky(float z) { return fmaxf(z, 0.01f * z); }
__device__ __forceinline__ float ex2(float x) {
    float r; asm("ex2.approx.f32 %0, %1;" : "=f"(r) : "f"(x)); return r;
}
// pack {lo half = w0, hi half = w1} as bf16x2
__device__ __forceinline__ uint32_t bfpack(float w0, float w1) {
    uint32_t r; asm("cvt.rn.bf16x2.f32 %0, %1, %2;" : "=r"(r) : "f"(w1), "f"(w0)); return r;
}
__device__ __forceinline__ void split_bf16(float v, unsigned short& hi, unsigned short& lo) {
    asm("cvt.rn.bf16.f32 %0, %1;" : "=h"(hi) : "f"(v));
    float hf = __uint_as_float(((uint32_t)hi) << 16);
    float r = v - hf;
    asm("cvt.rn.bf16.f32 %0, %1;" : "=h"(lo) : "f"(r));
}
__device__ __forceinline__ void ldsm4(uint32_t* r, uint32_t addr) {
    asm volatile("ldmatrix.sync.aligned.m8n8.x4.shared.b16 {%0,%1,%2,%3}, [%4];"
        : "=r"(r[0]), "=r"(r[1]), "=r"(r[2]), "=r"(r[3]) : "r"(addr));
}
__device__ __forceinline__ void mma16816(float* d, const uint32_t* a, uint32_t b0, uint32_t b1) {
    asm volatile(
        "mma.sync.aligned.m16n8k16.row.col.f32.bf16.bf16.f32 "
        "{%0,%1,%2,%3},{%4,%5,%6,%7},{%8,%9},{%0,%1,%2,%3};"
        : "+f"(d[0]), "+f"(d[1]), "+f"(d[2]), "+f"(d[3])
        : "r"(a[0]), "r"(a[1]), "r"(a[2]), "r"(a[3]), "r"(b0), "r"(b1));
}
// masked softmax weight (log2-domain inputs)
__device__ __forceinline__ float wgen(float s, float m, float t, int av) {
    float z = s + t;
    float w = ex2(fmaxf(z, 0.01f * z) - m);
    return (av > 0) ? w : 0.f;
}

// ---------------- P1: xw = x @ W, plus transposed bf16 hi/lo planes ----------
__global__ void proj_kernel(const float* __restrict__ xs, const float* __restrict__ xt,
                            const float* __restrict__ ws, const float* __restrict__ wt) {
    int y = blockIdx.y;
    const float* x = y ? xt : xs;
    const float* W = y ? wt : ws;
    float* out = y ? g_xw_t : g_xw_s;

    __shared__ float Wsm[IN_F * Dd];
    __shared__ float xsm[16 * IN_F];

    int tid = threadIdx.x;
    const float4* W4 = (const float4*)W;
    float4* Ws4 = (float4*)Wsm;
    for (int k = tid; k < IN_F * Dd / 4; k += 256) Ws4[k] = W4[k];

    int r0 = blockIdx.x * 16;
    const float4* x4 = (const float4*)(x + r0 * IN_F);
    float4* xs4 = (float4*)xsm;
    for (int k = tid; k < 16 * IN_F / 4; k += 256) xs4[k] = x4[k];
    __syncthreads();

    int c = tid & 63, rq = tid >> 6;
    float acc[4] = {0.f, 0.f, 0.f, 0.f};
    #pragma unroll 4
    for (int kk = 0; kk < IN_F; kk++) {
        float wv = Wsm[kk * Dd + c];
        #pragma unroll
        for (int k = 0; k < 4; k++)
            acc[k] += xsm[(rq + 4 * k) * IN_F + kk] * wv;
    }
    #pragma unroll
    for (int k = 0; k < 4; k++) {
        int row = r0 + rq + 4 * k;
        float v = acc[k];
        out[row * Dd + c] = v;
        unsigned short hi, lo;
        split_bf16(v, hi, lo);
        g_xT_hi[y][(size_t)c * Nn + row] = hi;
        g_xT_lo[y][(size_t)c * Nn + row] = lo;
    }
}

// ---------------- P2: projections onto a1/a2, PRE-SCALED by log2e -----------
__global__ void proj_vec_kernel(const float* __restrict__ a) {
    int y = blockIdx.y;
    const float* xw = y ? g_xw_t : g_xw_s;
    int w = threadIdx.x >> 5, lane = threadIdx.x & 31;
    int row = blockIdx.x * 8 + w;
    float v0 = xw[row * Dd + lane];
    float v1 = xw[row * Dd + 32 + lane];
    float p1 = v0 * a[lane] + v1 * a[32 + lane];
    float p2 = v0 * a[64 + lane] + v1 * a[96 + lane];
    #pragma unroll
    for (int o = 16; o; o >>= 1) {
        p1 += __shfl_down_sync(0xffffffffu, p1, o);
        p2 += __shfl_down_sync(0xffffffffu, p2, o);
    }
    if (lane == 0) {
        p1 *= LOG2E; p2 *= LOG2E;   // leaky(c*z)=c*leaky(z) for c>0
        if (y == 0) { g_s1[row] = p1; g_s2[row] = p2; }
        else        { g_t1[row] = p1; g_t2[row] = p2; }
    }
}

// ---------------- P3: maxes ---------------------------------------------------
__global__ void max_kernel() {
    __shared__ float sm[512];
    int tid = threadIdx.x;
    float m1 = -1e30f, m2 = -1e30f;
    for (int i = tid; i < Nn; i += 256) {
        m1 = fmaxf(m1, g_t2[i]);
        m2 = fmaxf(m2, g_s2[i]);
    }
    sm[tid] = m1; sm[256 + tid] = m2;
    __syncthreads();
    for (int s = 128; s; s >>= 1) {
        if (tid < s) {
            sm[tid]       = fmaxf(sm[tid],       sm[tid + s]);
            sm[256 + tid] = fmaxf(sm[256 + tid], sm[256 + tid + s]);
        }
        __syncthreads();
    }
    if (tid == 0) { g_max2[0] = sm[0]; g_max2[1] = sm[256]; }
}

// ---------------- main attention: reg A-frags, double-buffered B -------------
__global__ void __launch_bounds__(256, 3)
attn_kernel(const int* __restrict__ adj) {
    __shared__ __align__(16) char smc[32768];   // 2 bufs x {B hi 8K, B lo 8K}
    uint32_t smb = smem_u32(smc);

    int p = blockIdx.y, sp = blockIdx.z;
    int i0 = blockIdx.x * TI;
    int jbase = sp * JCH;
    const float* sv = p ? g_t1 : g_s1;
    const float* tv = p ? g_s2 : g_t2;
    const unsigned short* XH = g_xT_hi[p];
    const unsigned short* XL = g_xT_lo[p];
    float M = g_max2[p];

    int tid = threadIdx.x, wid = tid >> 5, lane = tid & 31;
    int r = lane >> 2, c = lane & 3;
    int iA = i0 + wid * 16 + r;    // rows this thread's A frags cover
    int iB = iA + 8;

    float sA = sv[iA], sB = sv[iB];
    float mA = leaky(sA + M), mB = leaky(sB + M);

    // B ldmatrix addressing (XOR swizzle: col ^ ((row&7)<<4))
    uint32_t bRow = (lane & 7) + ((lane >> 4) & 1) * 8;
    uint32_t bSel = ((lane >> 3) & 1) * 16;
    uint32_t bSwz = (lane & 7) << 4;
    uint32_t bBase = smb + bRow * 128;

    // B staging indices
    int sd = tid >> 2, scc = tid & 3;
    uint32_t sSwz = (sd & 7) << 4;
    uint32_t sRow = sd * 128;
    uint32_t so1 = sRow + ((scc * 16) ^ sSwz);
    uint32_t so2 = sRow + (((scc + 4) * 16) ^ sSwz);

    const uint32_t ONE2 = 0x3F803F80u;   // bf16x2 {1.0, 1.0}

    float acc[8][4];
    float den[4];
    #pragma unroll
    for (int n = 0; n < 8; n++)
        #pragma unroll
        for (int q = 0; q < 4; q++) acc[n][q] = 0.f;
    #pragma unroll
    for (int q = 0; q < 4; q++) den[q] = 0.f;

    // stage tile 0 into buffer 0
    {
        const uint4* srch = (const uint4*)(XH + (size_t)sd * Nn + jbase);
        const uint4* srcl = (const uint4*)(XL + (size_t)sd * Nn + jbase);
        *(uint4*)(smc + so1)        = srch[scc];
        *(uint4*)(smc + so2)        = srch[scc + 4];
        *(uint4*)(smc + 8192 + so1) = srcl[scc];
        *(uint4*)(smc + 8192 + so2) = srcl[scc + 4];
    }
    __syncthreads();

    for (int jt = 0; jt < NTILE; jt++) {
        int b = jt & 1;
        int j0 = jbase + jt * TJ;
        uint32_t bufB = bBase + b * 16384;

        // ---- prefetch next tile's B into the other buffer (rides under mma) ----
        if (jt + 1 < NTILE) {
            int jn = j0 + TJ;
            uint32_t obuf = (b ^ 1) * 16384;
            const uint4* srch = (const uint4*)(XH + (size_t)sd * Nn + jn);
            const uint4* srcl = (const uint4*)(XL + (size_t)sd * Nn + jn);
            *(uint4*)(smc + obuf + so1)        = srch[scc];
            *(uint4*)(smc + obuf + so2)        = srch[scc + 4];
            *(uint4*)(smc + obuf + 8192 + so1) = srcl[scc];
            *(uint4*)(smc + obuf + 8192 + so2) = srcl[scc + 4];
        }

        // ---- per K-chunk: jit adjacency, build A frags in regs, mma ----
        #pragma unroll
        for (int k = 0; k < 4; k++) {
            int jc = j0 + 16 * k + 2 * c;
            int av0, av1, av2, av3, av4, av5, av6, av7;
            if (p == 0) {
                const int* rowA = adj + (size_t)iA * Nn + jc;
                const int* rowB = adj + (size_t)iB * Nn + jc;
                int2 a0 = *(const int2*)(rowA);
                int2 a1 = *(const int2*)(rowA + 8);
                int2 b0 = *(const int2*)(rowB);
                int2 b1 = *(const int2*)(rowB + 8);
                av0 = a0.x; av1 = a0.y; av2 = a1.x; av3 = a1.y;
                av4 = b0.x; av5 = b0.y; av6 = b1.x; av7 = b1.y;
            } else {
                const int* c1 = adj + (size_t)jc * Nn;
                const int* c2 = c1 + Nn;
                const int* c3 = c1 + 8 * Nn;
                const int* c4 = c1 + 9 * Nn;
                av0 = c1[iA]; av1 = c2[iA]; av2 = c3[iA]; av3 = c4[iA];
                av4 = c1[iB]; av5 = c2[iB]; av6 = c3[iB]; av7 = c4[iB];
            }
            float2 t12 = *(const float2*)(tv + jc);
            float2 t34 = *(const float2*)(tv + jc + 8);

            float w0 = wgen(sA, mA, t12.x, av0);
            float w1 = wgen(sA, mA, t12.y, av1);
            float w2 = wgen(sA, mA, t34.x, av2);
            float w3 = wgen(sA, mA, t34.y, av3);
            float w4 = wgen(sB, mB, t12.x, av4);
            float w5 = wgen(sB, mB, t12.y, av5);
            float w6 = wgen(sB, mB, t34.x, av6);
            float w7 = wgen(sB, mB, t34.y, av7);

            uint32_t ah[4], al[4];
            ah[0] = bfpack(w0, w1);   // (row r,   k 2c..2c+1)
            ah[1] = bfpack(w4, w5);   // (row r+8, k 2c..2c+1)
            ah[2] = bfpack(w2, w3);   // (row r,   k 2c+8..)
            ah[3] = bfpack(w6, w7);   // (row r+8, k 2c+8..)
            {
                float h;
                h = __uint_as_float(ah[0] << 16);          float e0 = w0 - h;
                h = __uint_as_float(ah[0] & 0xFFFF0000u);  float e1 = w1 - h;
                al[0] = bfpack(e0, e1);
                h = __uint_as_float(ah[1] << 16);          e0 = w4 - h;
                h = __uint_as_float(ah[1] & 0xFFFF0000u);  e1 = w5 - h;
                al[1] = bfpack(e0, e1);
                h = __uint_as_float(ah[2] << 16);          e0 = w2 - h;
                h = __uint_as_float(ah[2] & 0xFFFF0000u);  e1 = w3 - h;
                al[2] = bfpack(e0, e1);
                h = __uint_as_float(ah[3] << 16);          e0 = w6 - h;
                h = __uint_as_float(ah[3] & 0xFFFF0000u);  e1 = w7 - h;
                al[3] = bfpack(e0, e1);
            }

            // denominator: ones-B
            mma16816(den, ah, ONE2, ONE2);
            mma16816(den, al, ONE2, ONE2);

            #pragma unroll
            for (int nn = 0; nn < 4; nn++) {
                uint32_t bh[4], bl[4];
                uint32_t boff = nn * 2048 + ((bSel + 32 * k) ^ bSwz);
                ldsm4(bh, bufB + boff);
                ldsm4(bl, bufB + 8192 + boff);
                mma16816(acc[2 * nn],     ah, bh[0], bh[1]);
                mma16816(acc[2 * nn + 1], ah, bh[2], bh[3]);
                mma16816(acc[2 * nn],     ah, bl[0], bl[1]);
                mma16816(acc[2 * nn + 1], ah, bl[2], bl[3]);
                mma16816(acc[2 * nn],     al, bh[0], bh[1]);
                mma16816(acc[2 * nn + 1], al, bh[2], bh[3]);
            }
        }
        __syncthreads();   // next buffer staged AND this buffer's reads done
    }

    // ---- write partials ----
    int buf = p * SPLITS + sp;
    int tg = lane & 3;
    float* nump = g_pnum + (size_t)buf * Nn * Dd;
    #pragma unroll
    for (int n = 0; n < 8; n++) {
        int col = n * 8 + tg * 2;
        *(float2*)(nump + (size_t)iA * Dd + col) = make_float2(acc[n][0], acc[n][1]);
        *(float2*)(nump + (size_t)iB * Dd + col) = make_float2(acc[n][2], acc[n][3]);
    }
    if (tg == 0) {
        g_pden[(size_t)buf * Nn + iA] = den[0];
        g_pden[(size_t)buf * Nn + iB] = den[2];
    }
}

// ---------------- finish: sum partials, normalize, bias + ELU ----------------
__global__ void finish_kernel(const float* __restrict__ bs, const float* __restrict__ bt,
                              float* __restrict__ out) {
    int warp = threadIdx.x >> 5, lane = threadIdx.x & 31;
    int rg = blockIdx.x * 8 + warp;
    int p = rg >> 13;
    int i = rg & (Nn - 1);
    const float* bias = p ? bt : bs;

    float2 acc = make_float2(0.f, 0.f);
    #pragma unroll
    for (int s = 0; s < SPLITS; s++) {
        const float2* np = (const float2*)(g_pnum + ((size_t)(p * SPLITS + s) * Nn + i) * Dd);
        float2 v = np[lane];
        acc.x += v.x; acc.y += v.y;
    }
    float den = (lane < SPLITS) ? g_pden[(size_t)(p * SPLITS + lane) * Nn + i] : 0.f;
    #pragma unroll
    for (int o = 16; o; o >>= 1) den += __shfl_xor_sync(0xffffffffu, den, o);
    float inv = 1.f / den;

    float v0 = acc.x * inv + bias[2 * lane];
    float v1 = acc.y * inv + bias[2 * lane + 1];
    v0 = (v0 > 0.f) ? v0 : expm1f(v0);
    v1 = (v1 > 0.f) ? v1 : expm1f(v1);
    ((float2*)(out + (size_t)rg * Dd))[lane] = make_float2(v0, v1);
}

// ---------------- launch ------------------------------------------------------
extern "C" void kernel_launch(void* const* d_in, const int* in_sizes, int n_in,
                              void* d_out, int out_size) {
    const float* xs  = (const float*)d_in[0];
    const float* xt  = (const float*)d_in[1];
    const int*   adj = (const int*)  d_in[2];
    const float* ws  = (const float*)d_in[3];
    const float* wt  = (const float*)d_in[4];
    const float* a   = (const float*)d_in[5];
    const float* bs  = (const float*)d_in[6];
    const float* bt  = (const float*)d_in[7];
    float* out = (float*)d_out;   // [2, 8192, 64]

    proj_kernel<<<dim3(Nn / 16, 2), 256>>>(xs, xt, ws, wt);
    proj_vec_kernel<<<dim3(Nn / 8, 2), 256>>>(a);
    max_kernel<<<1, 256>>>();
    attn_kernel<<<dim3(Nn / TI, 2, SPLITS), 256>>>(adj);
    finish_kernel<<<(2 * Nn) / 8, 256>>>(bs, bt, out);
}

// round 9
// speedup vs baseline: 3.8571x; 1.2178x over previous
#include <cuda_runtime.h>
#include <math.h>
#include <stdint.h>

#define Nn 8192
#define Dd 64
#define IN_F 128
#define TI 128
#define TJ 64
#define SPLITS 8
#define JCH (Nn / SPLITS)     // 1024
#define NTILE (JCH / TJ)      // 16
#define LOG2E 1.4426950408889634f

#define BITS_OFF 32768        // smem: 2x16KB B planes, then 2x1KB mask blocks

// ---------------- device scratch ---------------------------------------------
__device__ float g_xw_s[Nn * Dd];
__device__ float g_xw_t[Nn * Dd];
__device__ float g_s1[Nn], g_s2[Nn], g_t1[Nn], g_t2[Nn];   // pre-scaled by log2e
__device__ float g_max2[2];
__device__ unsigned short g_xT_hi[2][Dd * Nn];   // [side][d][j]
__device__ unsigned short g_xT_lo[2][Dd * Nn];
__device__ float g_pnum[2 * SPLITS * Nn * Dd];
__device__ float g_pden[2 * SPLITS * Nn];
__device__ uint32_t g_adjB[(size_t)Nn * (Nn / 32)];   // 8 MB bit-packed adjacency

// ---------------- helpers -----------------------------------------------------
__device__ __forceinline__ uint32_t smem_u32(const void* p) {
    uint32_t a;
    asm("{ .reg .u64 t; cvta.to.shared.u64 t, %1; cvt.u32.u64 %0, t; }" : "=r"(a) : "l"(p));
    return a;
}
__device__ __forceinline__ float leaky(float z) { return fmaxf(z, 0.01f * z); }
__device__ __forceinline__ float ex2(float x) {
    float r; asm("ex2.approx.f32 %0, %1;" : "=f"(r) : "f"(x)); return r;
}
__device__ __forceinline__ uint32_t bfpack(float w0, float w1) {
    uint32_t r; asm("cvt.rn.bf16x2.f32 %0, %1, %2;" : "=r"(r) : "f"(w1), "f"(w0)); return r;
}
__device__ __forceinline__ void split_bf16(float v, unsigned short& hi, unsigned short& lo) {
    asm("cvt.rn.bf16.f32 %0, %1;" : "=h"(hi) : "f"(v));
    float hf = __uint_as_float(((uint32_t)hi) << 16);
    float r = v - hf;
    asm("cvt.rn.bf16.f32 %0, %1;" : "=h"(lo) : "f"(r));
}
__device__ __forceinline__ void ldsm4(uint32_t* r, uint32_t addr) {
    asm volatile("ldmatrix.sync.aligned.m8n8.x4.shared.b16 {%0,%1,%2,%3}, [%4];"
        : "=r"(r[0]), "=r"(r[1]), "=r"(r[2]), "=r"(r[3]) : "r"(addr));
}
__device__ __forceinline__ void mma16816(float* d, const uint32_t* a, uint32_t b0, uint32_t b1) {
    asm volatile(
        "mma.sync.aligned.m16n8k16.row.col.f32.bf16.bf16.f32 "
        "{%0,%1,%2,%3},{%4,%5,%6,%7},{%8,%9},{%0,%1,%2,%3};"
        : "+f"(d[0]), "+f"(d[1]), "+f"(d[2]), "+f"(d[3])
        : "r"(a[0]), "r"(a[1]), "r"(a[2]), "r"(a[3]), "r"(b0), "r"(b1));
}
__device__ __forceinline__ void cpa16(uint32_t d, const void* s) {
    asm volatile("cp.async.cg.shared.global [%0], [%1], 16;" :: "r"(d), "l"(s));
}
__device__ __forceinline__ void cpa8(uint32_t d, const void* s) {
    asm volatile("cp.async.ca.shared.global [%0], [%1], 8;" :: "r"(d), "l"(s));
}
#define CP_COMMIT() asm volatile("cp.async.commit_group;" ::: "memory")
#define CP_WAIT0()  asm volatile("cp.async.wait_group 0;" ::: "memory")

// masked softmax weight (log2-domain inputs, mask from bit)
__device__ __forceinline__ float wgen(float s, float m, float t, uint32_t q, int bit) {
    float z = s + t;
    float w = ex2(fmaxf(z, 0.01f * z) - m);
    return ((q >> bit) & 1u) ? w : 0.f;
}

// ---------------- P0: pack adjacency rows to bits ----------------------------
__global__ void pack_kernel(const int* __restrict__ adj) {
    int i = blockIdx.x;
    int w8 = threadIdx.x >> 5, lane = threadIdx.x & 31;
    const int* row = adj + (size_t)i * Nn;
    uint32_t mine = 0;
    #pragma unroll 4
    for (int k = 0; k < 32; k++) {
        int word = w8 * 32 + k;
        uint32_t b = __ballot_sync(0xffffffffu, row[word * 32 + lane] > 0);
        if (lane == k) mine = b;
    }
    g_adjB[(size_t)i * (Nn / 32) + w8 * 32 + lane] = mine;
}

// ---------------- P1: xw = x @ W, plus transposed bf16 hi/lo planes ----------
__global__ void proj_kernel(const float* __restrict__ xs, const float* __restrict__ xt,
                            const float* __restrict__ ws, const float* __restrict__ wt) {
    int y = blockIdx.y;
    const float* x = y ? xt : xs;
    const float* W = y ? wt : ws;
    float* out = y ? g_xw_t : g_xw_s;

    __shared__ float Wsm[IN_F * Dd];
    __shared__ float xsm[16 * IN_F];

    int tid = threadIdx.x;
    const float4* W4 = (const float4*)W;
    float4* Ws4 = (float4*)Wsm;
    for (int k = tid; k < IN_F * Dd / 4; k += 256) Ws4[k] = W4[k];

    int r0 = blockIdx.x * 16;
    const float4* x4 = (const float4*)(x + r0 * IN_F);
    float4* xs4 = (float4*)xsm;
    for (int k = tid; k < 16 * IN_F / 4; k += 256) xs4[k] = x4[k];
    __syncthreads();

    int c = tid & 63, rq = tid >> 6;
    float acc[4] = {0.f, 0.f, 0.f, 0.f};
    #pragma unroll 4
    for (int kk = 0; kk < IN_F; kk++) {
        float wv = Wsm[kk * Dd + c];
        #pragma unroll
        for (int k = 0; k < 4; k++)
            acc[k] += xsm[(rq + 4 * k) * IN_F + kk] * wv;
    }
    #pragma unroll
    for (int k = 0; k < 4; k++) {
        int row = r0 + rq + 4 * k;
        float v = acc[k];
        out[row * Dd + c] = v;
        unsigned short hi, lo;
        split_bf16(v, hi, lo);
        g_xT_hi[y][(size_t)c * Nn + row] = hi;
        g_xT_lo[y][(size_t)c * Nn + row] = lo;
    }
}

// ---------------- P2: projections onto a1/a2, PRE-SCALED by log2e -----------
__global__ void proj_vec_kernel(const float* __restrict__ a) {
    int y = blockIdx.y;
    const float* xw = y ? g_xw_t : g_xw_s;
    int w = threadIdx.x >> 5, lane = threadIdx.x & 31;
    int row = blockIdx.x * 8 + w;
    float v0 = xw[row * Dd + lane];
    float v1 = xw[row * Dd + 32 + lane];
    float p1 = v0 * a[lane] + v1 * a[32 + lane];
    float p2 = v0 * a[64 + lane] + v1 * a[96 + lane];
    #pragma unroll
    for (int o = 16; o; o >>= 1) {
        p1 += __shfl_down_sync(0xffffffffu, p1, o);
        p2 += __shfl_down_sync(0xffffffffu, p2, o);
    }
    if (lane == 0) {
        p1 *= LOG2E; p2 *= LOG2E;   // leaky(c*z)=c*leaky(z) for c>0
        if (y == 0) { g_s1[row] = p1; g_s2[row] = p2; }
        else        { g_t1[row] = p1; g_t2[row] = p2; }
    }
}

// ---------------- P3: maxes ---------------------------------------------------
__global__ void max_kernel() {
    __shared__ float sm[512];
    int tid = threadIdx.x;
    float m1 = -1e30f, m2 = -1e30f;
    for (int i = tid; i < Nn; i += 256) {
        m1 = fmaxf(m1, g_t2[i]);
        m2 = fmaxf(m2, g_s2[i]);
    }
    sm[tid] = m1; sm[256 + tid] = m2;
    __syncthreads();
    for (int s = 128; s; s >>= 1) {
        if (tid < s) {
            sm[tid]       = fmaxf(sm[tid],       sm[tid + s]);
            sm[256 + tid] = fmaxf(sm[256 + tid], sm[256 + tid + s]);
        }
        __syncthreads();
    }
    if (tid == 0) { g_max2[0] = sm[0]; g_max2[1] = sm[256]; }
}

// ---------------- main attention: cp.async staging + bitmask -----------------
__global__ void __launch_bounds__(256, 3)
attn_kernel() {
    __shared__ __align__(16) char smc[32768 + 2048];
    uint32_t smb = smem_u32(smc);

    int p = blockIdx.y, sp = blockIdx.z;
    int i0 = blockIdx.x * TI;
    int jbase = sp * JCH;
    const float* sv = p ? g_t1 : g_s1;
    const float* tv = p ? g_s2 : g_t2;
    const unsigned short* XH = g_xT_hi[p];
    const unsigned short* XL = g_xT_lo[p];
    float M = g_max2[p];

    int tid = threadIdx.x, wid = tid >> 5, lane = tid & 31;
    int r = lane >> 2, c = lane & 3;
    int iA = i0 + wid * 16 + r;
    int iB = iA + 8;

    float sA = sv[iA], sB = sv[iB];
    float mA = leaky(sA + M), mB = leaky(sB + M);

    // B ldmatrix addressing (XOR swizzle: col ^ ((row&7)<<4))
    uint32_t bRow = (lane & 7) + ((lane >> 4) & 1) * 8;
    uint32_t bSel = ((lane >> 3) & 1) * 16;
    uint32_t bSwz = (lane & 7) << 4;
    uint32_t bBase = smb + bRow * 128;

    // B staging indices
    int sd = tid >> 2, scc = tid & 3;
    uint32_t sSwz = (sd & 7) << 4;
    uint32_t sRow = sd * 128;
    uint32_t so1 = sRow + ((scc * 16) ^ sSwz);
    uint32_t so2 = sRow + (((scc + 4) * 16) ^ sSwz);

    const uint32_t ONE2 = 0x3F803F80u;   // bf16x2 {1.0, 1.0}
    const uint32_t WDS = Nn / 32;        // adjB row stride in words

    float acc[8][4];
    float den[4];
    #pragma unroll
    for (int n = 0; n < 8; n++)
        #pragma unroll
        for (int q = 0; q < 4; q++) acc[n][q] = 0.f;
    #pragma unroll
    for (int q = 0; q < 4; q++) den[q] = 0.f;

    // ---- stage tile 0 into buffer 0 (cp.async) ----
    {
        const char* srch = (const char*)(XH + (size_t)sd * Nn + jbase);
        const char* srcl = (const char*)(XL + (size_t)sd * Nn + jbase);
        cpa16(smb + so1,        srch + scc * 16);
        cpa16(smb + so2,        srch + (scc + 4) * 16);
        cpa16(smb + 8192 + so1, srcl + scc * 16);
        cpa16(smb + 8192 + so2, srcl + (scc + 4) * 16);
        if (p == 0) {
            if (tid < TI) cpa8(smb + BITS_OFF + tid * 8,
                               g_adjB + (size_t)(i0 + tid) * WDS + (jbase >> 5));
        } else {
            if (tid < TJ) cpa16(smb + BITS_OFF + tid * 16,
                                g_adjB + (size_t)(jbase + tid) * WDS + (i0 >> 5));
        }
        CP_COMMIT();
        CP_WAIT0();
    }
    __syncthreads();

    for (int jt = 0; jt < NTILE; jt++) {
        int b = jt & 1;
        int j0 = jbase + jt * TJ;
        uint32_t bufB = bBase + b * 16384;
        const char* bitsCur = smc + BITS_OFF + b * 1024;

        // ---- prefetch next tile into the other buffer (async, no stall) ----
        if (jt + 1 < NTILE) {
            int jn = j0 + TJ;
            uint32_t ob = (b ^ 1);
            uint32_t obuf = ob * 16384;
            const char* srch = (const char*)(XH + (size_t)sd * Nn + jn);
            const char* srcl = (const char*)(XL + (size_t)sd * Nn + jn);
            cpa16(smb + obuf + so1,        srch + scc * 16);
            cpa16(smb + obuf + so2,        srch + (scc + 4) * 16);
            cpa16(smb + obuf + 8192 + so1, srcl + scc * 16);
            cpa16(smb + obuf + 8192 + so2, srcl + (scc + 4) * 16);
            if (p == 0) {
                if (tid < TI) cpa8(smb + BITS_OFF + ob * 1024 + tid * 8,
                                   g_adjB + (size_t)(i0 + tid) * WDS + (jn >> 5));
            } else {
                if (tid < TJ) cpa16(smb + BITS_OFF + ob * 1024 + tid * 16,
                                    g_adjB + (size_t)(jn + tid) * WDS + (i0 >> 5));
            }
            CP_COMMIT();
        }

        // ---- mask words for this tile ----
        uint2 vA, vB;
        int wsel = wid >> 1;
        int bitA = ((wid & 1) << 4) + r;
        if (p == 0) {
            vA = *(const uint2*)(bitsCur + (wid * 16 + r) * 8);
            vB = *(const uint2*)(bitsCur + (wid * 16 + r + 8) * 8);
        }

        // ---- per K-chunk: build A frags in regs, mma ----
        #pragma unroll
        for (int k = 0; k < 4; k++) {
            int jc = j0 + 16 * k + 2 * c;
            float2 t12 = *(const float2*)(tv + jc);
            float2 t34 = *(const float2*)(tv + jc + 8);

            float w0, w1, w2, w3, w4, w5, w6, w7;
            if (p == 0) {
                uint32_t qA = (k < 2) ? vA.x : vA.y;
                uint32_t qB = (k < 2) ? vB.x : vB.y;
                int b0 = ((k & 1) << 4) + 2 * c;
                w0 = wgen(sA, mA, t12.x, qA, b0);
                w1 = wgen(sA, mA, t12.y, qA, b0 + 1);
                w2 = wgen(sA, mA, t34.x, qA, b0 + 8);
                w3 = wgen(sA, mA, t34.y, qA, b0 + 9);
                w4 = wgen(sB, mB, t12.x, qB, b0);
                w5 = wgen(sB, mB, t12.y, qB, b0 + 1);
                w6 = wgen(sB, mB, t34.x, qB, b0 + 8);
                w7 = wgen(sB, mB, t34.y, qB, b0 + 9);
            } else {
                int rowb = 16 * k + 2 * c;
                uint32_t q0 = *(const uint32_t*)(bitsCur + (rowb    ) * 16 + wsel * 4);
                uint32_t q1 = *(const uint32_t*)(bitsCur + (rowb + 1) * 16 + wsel * 4);
                uint32_t q2 = *(const uint32_t*)(bitsCur + (rowb + 8) * 16 + wsel * 4);
                uint32_t q3 = *(const uint32_t*)(bitsCur + (rowb + 9) * 16 + wsel * 4);
                w0 = wgen(sA, mA, t12.x, q0, bitA);
                w1 = wgen(sA, mA, t12.y, q1, bitA);
                w2 = wgen(sA, mA, t34.x, q2, bitA);
                w3 = wgen(sA, mA, t34.y, q3, bitA);
                w4 = wgen(sB, mB, t12.x, q0, bitA + 8);
                w5 = wgen(sB, mB, t12.y, q1, bitA + 8);
                w6 = wgen(sB, mB, t34.x, q2, bitA + 8);
                w7 = wgen(sB, mB, t34.y, q3, bitA + 8);
            }

            uint32_t ah[4], al[4];
            ah[0] = bfpack(w0, w1);
            ah[1] = bfpack(w4, w5);
            ah[2] = bfpack(w2, w3);
            ah[3] = bfpack(w6, w7);
            {
                float h;
                h = __uint_as_float(ah[0] << 16);          float e0 = w0 - h;
                h = __uint_as_float(ah[0] & 0xFFFF0000u);  float e1 = w1 - h;
                al[0] = bfpack(e0, e1);
                h = __uint_as_float(ah[1] << 16);          e0 = w4 - h;
                h = __uint_as_float(ah[1] & 0xFFFF0000u);  e1 = w5 - h;
                al[1] = bfpack(e0, e1);
                h = __uint_as_float(ah[2] << 16);          e0 = w2 - h;
                h = __uint_as_float(ah[2] & 0xFFFF0000u);  e1 = w3 - h;
                al[2] = bfpack(e0, e1);
                h = __uint_as_float(ah[3] << 16);          e0 = w6 - h;
                h = __uint_as_float(ah[3] & 0xFFFF0000u);  e1 = w7 - h;
                al[3] = bfpack(e0, e1);
            }

            mma16816(den, ah, ONE2, ONE2);
            mma16816(den, al, ONE2, ONE2);

            #pragma unroll
            for (int nn = 0; nn < 4; nn++) {
                uint32_t bh[4], bl[4];
                uint32_t boff = nn * 2048 + ((bSel + 32 * k) ^ bSwz);
                ldsm4(bh, bufB + boff);
                ldsm4(bl, bufB + 8192 + boff);
                mma16816(acc[2 * nn],     ah, bh[0], bh[1]);
                mma16816(acc[2 * nn + 1], ah, bh[2], bh[3]);
                mma16816(acc[2 * nn],     ah, bl[0], bl[1]);
                mma16816(acc[2 * nn + 1], ah, bl[2], bl[3]);
                mma16816(acc[2 * nn],     al, bh[0], bh[1]);
                mma16816(acc[2 * nn + 1], al, bh[2], bh[3]);
            }
        }
        CP_WAIT0();
        __syncthreads();
    }

    // ---- write partials ----
    int buf = p * SPLITS + sp;
    int tg = lane & 3;
    float* nump = g_pnum + (size_t)buf * Nn * Dd;
    #pragma unroll
    for (int n = 0; n < 8; n++) {
        int col = n * 8 + tg * 2;
        *(float2*)(nump + (size_t)iA * Dd + col) = make_float2(acc[n][0], acc[n][1]);
        *(float2*)(nump + (size_t)iB * Dd + col) = make_float2(acc[n][2], acc[n][3]);
    }
    if (tg == 0) {
        g_pden[(size_t)buf * Nn + iA] = den[0];
        g_pden[(size_t)buf * Nn + iB] = den[2];
    }
}

// ---------------- finish: sum partials, normalize, bias + ELU ----------------
__global__ void finish_kernel(const float* __restrict__ bs, const float* __restrict__ bt,
                              float* __restrict__ out) {
    int warp = threadIdx.x >> 5, lane = threadIdx.x & 31;
    int rg = blockIdx.x * 8 + warp;
    int p = rg >> 13;
    int i = rg & (Nn - 1);
    const float* bias = p ? bt : bs;

    float2 acc = make_float2(0.f, 0.f);
    #pragma unroll
    for (int s = 0; s < SPLITS; s++) {
        const float2* np = (const float2*)(g_pnum + ((size_t)(p * SPLITS + s) * Nn + i) * Dd);
        float2 v = np[lane];
        acc.x += v.x; acc.y += v.y;
    }
    float den = (lane < SPLITS) ? g_pden[(size_t)(p * SPLITS + lane) * Nn + i] : 0.f;
    #pragma unroll
    for (int o = 16; o; o >>= 1) den += __shfl_xor_sync(0xffffffffu, den, o);
    float inv = 1.f / den;

    float v0 = acc.x * inv + bias[2 * lane];
    float v1 = acc.y * inv + bias[2 * lane + 1];
    v0 = (v0 > 0.f) ? v0 : expm1f(v0);
    v1 = (v1 > 0.f) ? v1 : expm1f(v1);
    ((float2*)(out + (size_t)rg * Dd))[lane] = make_float2(v0, v1);
}

// ---------------- launch ------------------------------------------------------
extern "C" void kernel_launch(void* const* d_in, const int* in_sizes, int n_in,
                              void* d_out, int out_size) {
    const float* xs  = (const float*)d_in[0];
    const float* xt  = (const float*)d_in[1];
    const int*   adj = (const int*)  d_in[2];
    const float* ws  = (const float*)d_in[3];
    const float* wt  = (const float*)d_in[4];
    const float* a   = (const float*)d_in[5];
    const float* bs  = (const float*)d_in[6];
    const float* bt  = (const float*)d_in[7];
    float* out = (float*)d_out;   // [2, 8192, 64]

    pack_kernel<<<Nn, 256>>>(adj);
    proj_kernel<<<dim3(Nn / 16, 2), 256>>>(xs, xt, ws, wt);
    proj_vec_kernel<<<dim3(Nn / 8, 2), 256>>>(a);
    max_kernel<<<1, 256>>>();
    attn_kernel<<<dim3(Nn / TI, 2, SPLITS), 256>>>();
    finish_kernel<<<(2 * Nn) / 8, 256>>>(bs, bt, out);
}